// round 9
// baseline (speedup 1.0000x reference)
#include <cuda_runtime.h>

#define BATCH  32768
#define SEQT   28
#define DIMI   32
#define HH     32
#define NSTEPS 10

// MUFU.EX2-based transcendentals (~1e-7 rel err)
__device__ __forceinline__ float fast_tanh(float x) {
    float e = __expf(2.0f * x);
    return 1.0f - __fdividef(2.0f, e + 1.0f);
}
__device__ __forceinline__ float fast_sigmoid(float x) {
    return __fdividef(1.0f, 1.0f + __expf(-x));
}

struct __align__(16) SW {
    float W1[HH * HH];
    float W2[HH * HH];
    float b1[HH];
    float b2[HH];
    float Wih[3 * HH * DIMI];
    float Whh[3 * HH * HH];
    float bih[3 * HH];
    float bhh[3 * HH];
};

// Partial matvec: v = this lane's 16 input elems (k in [q16, q16+16)).
//   pA[i] (+)= sum_k v_k * W[q16+i][k]        (own j-half)
//   pB[i] (+)= sum_k v_k * W[(16-q16)+i][k]   (partner's j-half)
// NOTE: unroll 4 on the i-loop is deliberate — full unroll makes ptxas
// front-batch up to 32 LDS.128 results and balloon register allocation.
template <bool ACC>
__device__ __forceinline__ void matvec_half(const float* __restrict__ v,
                                            const float* __restrict__ Wbase,
                                            int q16,
                                            float* __restrict__ pA,
                                            float* __restrict__ pB) {
    const int jB = 16 - q16;
#pragma unroll 4
    for (int i = 0; i < 16; i++) {
        const float4* rA = (const float4*)(Wbase + (q16 + i) * HH + q16);
        const float4* rB = (const float4*)(Wbase + (jB + i) * HH + q16);
        float sA = 0.0f, sB = 0.0f;
#pragma unroll
        for (int c = 0; c < 4; c++) {
            float4 wa = rA[c];
            float4 wb = rB[c];
            sA = fmaf(v[4 * c + 0], wa.x, sA);
            sA = fmaf(v[4 * c + 1], wa.y, sA);
            sA = fmaf(v[4 * c + 2], wa.z, sA);
            sA = fmaf(v[4 * c + 3], wa.w, sA);
            sB = fmaf(v[4 * c + 0], wb.x, sB);
            sB = fmaf(v[4 * c + 1], wb.y, sB);
            sB = fmaf(v[4 * c + 2], wb.z, sB);
            sB = fmaf(v[4 * c + 3], wb.w, sB);
        }
        if (ACC) { pA[i] += sA; pB[i] += sB; }
        else     { pA[i] = sA;  pB[i] = sB; }
    }
}

// full dot for own j-half = own partial + partner's cross partial (+ bias row)
#define COMBINE_BIAS(dst, pA, pB, brow)                                   \
    _Pragma("unroll")                                                     \
    for (int i = 0; i < 16; i++)                                          \
        dst[i] = pA[i] + __shfl_xor_sync(0xffffffffu, pB[i], 1) + (brow)[i];

// ---------- RK4 over one span ----------
__device__ __forceinline__ void rk4(float* __restrict__ y, float dt, int q16,
                                    const SW& s) {
    const float dt6 = dt * (1.0f / 6.0f);
    const float dt3 = dt * (1.0f / 3.0f);
    const float dth = dt * 0.5f;
    const float* b1q = s.b1 + q16;
    const float* b2q = s.b2 + q16;
#pragma unroll 1
    for (int st = 0; st < NSTEPS; st++) {
        float acc[16], yt[16];
#pragma unroll
        for (int i = 0; i < 16; i++) { acc[i] = y[i]; yt[i] = y[i]; }
#pragma unroll 1
        for (int sidx = 0; sidx < 4; sidx++) {
            const float ca = (sidx == 1 || sidx == 2) ? dt3 : dt6;
            const float cy = (sidx >= 2) ? dt : dth;
            float pA[16], pB[16], t[16];
            matvec_half<false>(yt, s.W1, q16, pA, pB);
            COMBINE_BIAS(t, pA, pB, b1q);
#pragma unroll
            for (int i = 0; i < 16; i++)
                t[i] = fast_tanh(t[i]);
            matvec_half<false>(t, s.W2, q16, pA, pB);
            COMBINE_BIAS(t, pA, pB, b2q);      // t now holds k-stage value
#pragma unroll
            for (int i = 0; i < 16; i++) {
                acc[i] = fmaf(ca, t[i], acc[i]);
                yt[i]  = fmaf(cy, t[i], y[i]);   // dead at sidx==3
            }
        }
#pragma unroll
        for (int i = 0; i < 16; i++) y[i] = acc[i];
    }
}

// ---------- GRU cell (PyTorch gate order r,z,n) ----------
__device__ __forceinline__ void gru(float* __restrict__ h,
                                    const float* __restrict__ xg,
                                    int q16, const SW& s) {
    float x[16];
    const float4* x4 = (const float4*)xg;
#pragma unroll
    for (int c = 0; c < 4; c++) {
        float4 v = x4[c];
        x[4 * c] = v.x; x[4 * c + 1] = v.y; x[4 * c + 2] = v.z; x[4 * c + 3] = v.w;
    }
    float pA[16], pB[16], r[16], z[16];

    // r gate: accumulate both matvecs in partial space, single combine
    matvec_half<false>(x, s.Wih, q16, pA, pB);
    matvec_half<true>(h, s.Whh, q16, pA, pB);
    COMBINE_BIAS(r, pA, pB, s.bih + q16);
#pragma unroll
    for (int i = 0; i < 16; i++)
        r[i] = fast_sigmoid(r[i] + s.bhh[q16 + i]);

    // z gate
    matvec_half<false>(x, s.Wih + HH * DIMI, q16, pA, pB);
    matvec_half<true>(h, s.Whh + HH * HH, q16, pA, pB);
    COMBINE_BIAS(z, pA, pB, s.bih + HH + q16);
#pragma unroll
    for (int i = 0; i < 16; i++)
        z[i] = fast_sigmoid(z[i] + s.bhh[HH + q16 + i]);

    // n gate: gi and gh kept separate (r scales only the h-path)
    float gi[16], gh[16];
    matvec_half<false>(x, s.Wih + 2 * HH * DIMI, q16, pA, pB);
    COMBINE_BIAS(gi, pA, pB, s.bih + 2 * HH + q16);
    matvec_half<false>(h, s.Whh + 2 * HH * HH, q16, pA, pB);
    COMBINE_BIAS(gh, pA, pB, s.bhh + 2 * HH + q16);
#pragma unroll
    for (int i = 0; i < 16; i++) {
        float n = fast_tanh(gi[i] + r[i] * gh[i]);
        h[i] = (1.0f - z[i]) * n + z[i] * h[i];
    }
}

__device__ __forceinline__ void store_relu(float* __restrict__ dst,
                                           const float* __restrict__ y) {
    float4* d4 = (float4*)dst;
#pragma unroll
    for (int c = 0; c < 4; c++)
        d4[c] = make_float4(fmaxf(y[4 * c], 0.0f), fmaxf(y[4 * c + 1], 0.0f),
                            fmaxf(y[4 * c + 2], 0.0f), fmaxf(y[4 * c + 3], 0.0f));
}

__global__ void __launch_bounds__(128, 3) ode_gru_kernel(
    const float* __restrict__ inputs,   // [B, 28, 32]
    const float* __restrict__ h0,       // [B, 32]
    const float* __restrict__ Wih, const float* __restrict__ Whh,
    const float* __restrict__ bih, const float* __restrict__ bhh,
    const float* __restrict__ W1,  const float* __restrict__ b1,
    const float* __restrict__ W2,  const float* __restrict__ b2,
    float* __restrict__ out)            // [2, B, 32]
{
    __shared__ SW s;
    const int tid = threadIdx.x;

    for (int i = tid; i < HH * HH; i += 128) { s.W1[i] = W1[i]; s.W2[i] = W2[i]; }
    for (int i = tid; i < 3 * HH * DIMI; i += 128) { s.Wih[i] = Wih[i]; s.Whh[i] = Whh[i]; }
    if (tid < HH)     { s.b1[tid]  = b1[tid];  s.b2[tid]  = b2[tid]; }
    if (tid < 3 * HH) { s.bih[tid] = bih[tid]; s.bhh[tid] = bhh[tid]; }
    __syncthreads();

    const int gt  = blockIdx.x * 128 + tid;  // 2 lanes per batch row
    const int row = gt >> 1;
    const int q16 = (gt & 1) * 16;           // this lane's element-half offset

    float y[16];
    const float4* h04 = (const float4*)(h0 + (size_t)row * HH + q16);
#pragma unroll
    for (int c = 0; c < 4; c++) {
        float4 v = h04[c];
        y[4 * c] = v.x; y[4 * c + 1] = v.y; y[4 * c + 2] = v.z; y[4 * c + 3] = v.w;
    }

    const float* xbase = inputs + (size_t)row * SEQT * DIMI + q16;

    rk4(y, 0.1f, q16, s);                         // initial span [0,1]
#pragma unroll 1
    for (int t = 0; t < SEQT - 1; t++) {          // steps 0..26
        gru(y, xbase + t * DIMI, q16, s);
        rk4(y, 0.1f, q16, s);
    }
    // step 27: GRU -> h_start, then span-14 integration -> h_end
    gru(y, xbase + (SEQT - 1) * DIMI, q16, s);
    store_relu(out + (size_t)row * HH + q16, y);
    rk4(y, 1.4f, q16, s);
    store_relu(out + ((size_t)BATCH + row) * HH + q16, y);
}

extern "C" void kernel_launch(void* const* d_in, const int* in_sizes, int n_in,
                              void* d_out, int out_size) {
    (void)in_sizes; (void)n_in; (void)out_size;
    ode_gru_kernel<<<(2 * BATCH) / 128, 128>>>(
        (const float*)d_in[0], (const float*)d_in[1],
        (const float*)d_in[2], (const float*)d_in[3],
        (const float*)d_in[4], (const float*)d_in[5],
        (const float*)d_in[6], (const float*)d_in[7],
        (const float*)d_in[8], (const float*)d_in[9],
        (float*)d_out);
}

// round 10
// speedup vs baseline: 1.9599x; 1.9599x over previous
#include <cuda_runtime.h>

typedef unsigned long long u64;

#define BATCH  32768
#define SEQT   28
#define DIMI   32
#define HH     32
#define NSTEPS 10

// ---------- packed f32x2 helpers (sm_103a) ----------
__device__ __forceinline__ u64 ffma2(u64 a, u64 b, u64 c) {
    u64 d;
    asm("fma.rn.f32x2 %0, %1, %2, %3;" : "=l"(d) : "l"(a), "l"(b), "l"(c));
    return d;
}
__device__ __forceinline__ u64 fadd2(u64 a, u64 b) {
    u64 d;
    asm("add.rn.f32x2 %0, %1, %2;" : "=l"(d) : "l"(a), "l"(b));
    return d;
}
__device__ __forceinline__ u64 pack2(float a, float b) {
    u64 d;
    asm("mov.b64 %0, {%1, %2};" : "=l"(d) : "f"(a), "f"(b));
    return d;
}
__device__ __forceinline__ void unpack2(u64 a, float& lo, float& hi) {
    asm("mov.b64 {%0, %1}, %2;" : "=f"(lo), "=f"(hi) : "l"(a));
}
__device__ __forceinline__ float hsum2(u64 a) {
    float lo, hi; unpack2(a, lo, hi);
    return lo + hi;
}

// MUFU.EX2-based transcendentals (~1e-7 rel err)
__device__ __forceinline__ float fast_tanh(float x) {
    float e = __expf(2.0f * x);
    return 1.0f - __fdividef(2.0f, e + 1.0f);
}
__device__ __forceinline__ float fast_sigmoid(float x) {
    return __fdividef(1.0f, 1.0f + __expf(-x));
}

struct __align__(16) SW {
    float W1[HH * HH];
    float W2[HH * HH];
    float b1[HH];
    float b2[HH];
    float Wih[3 * HH * DIMI];
    float Whh[3 * HH * HH];
    float bih[3 * HH];
    float bhh[3 * HH];
};

// Packed partial matvec: vp = 8 f32x2 pairs = this lane's 16 input elems
// (k in [q16, q16+16)).
//   pA[i] (+)= sum_k v_k * W[q16+i][k]        (own j-half)
//   pB[i] (+)= sum_k v_k * W[(16-q16)+i][k]   (partner's j-half)
// unroll 4 is load-bearing: full unroll makes ptxas front-batch all weight
// loads and balloon/spill registers (measured R2/R5/R6/R7 vs R8).
template <bool ACC>
__device__ __forceinline__ void matvec_half(const u64* __restrict__ vp,
                                            const float* __restrict__ Wbase,
                                            int q16,
                                            float* __restrict__ pA,
                                            float* __restrict__ pB) {
    const int jB = 16 - q16;
#pragma unroll 4
    for (int i = 0; i < 16; i++) {
        const ulonglong2* rA = (const ulonglong2*)(Wbase + (q16 + i) * HH + q16);
        const ulonglong2* rB = (const ulonglong2*)(Wbase + (jB + i) * HH + q16);
        u64 a0 = 0ull, a1 = 0ull, b0 = 0ull, b1 = 0ull;
#pragma unroll
        for (int c = 0; c < 4; c++) {
            ulonglong2 wa = rA[c];
            ulonglong2 wb = rB[c];
            a0 = ffma2(vp[2 * c],     wa.x, a0);
            a1 = ffma2(vp[2 * c + 1], wa.y, a1);
            b0 = ffma2(vp[2 * c],     wb.x, b0);
            b1 = ffma2(vp[2 * c + 1], wb.y, b1);
        }
        float sA = hsum2(fadd2(a0, a1));
        float sB = hsum2(fadd2(b0, b1));
        if (ACC) { pA[i] += sA; pB[i] += sB; }
        else     { pA[i] = sA;  pB[i] = sB; }
    }
}

// full dot of output j = q16+i:  pA[i] + partner's cross partial
#define CMB(pA, pB, i) (pA[i] + __shfl_xor_sync(0xffffffffu, pB[i], 1))

// ---------- RK4 over one span, packed state yp[8] ----------
__device__ __forceinline__ void rk4(u64* __restrict__ yp, float dt, int q16,
                                    const SW& s) {
    const float dt6 = dt * (1.0f / 6.0f);
    const float dt3 = dt * (1.0f / 3.0f);
    const float dth = dt * 0.5f;
    const float* b1q = s.b1 + q16;
    const float* b2q = s.b2 + q16;
#pragma unroll 1
    for (int st = 0; st < NSTEPS; st++) {
        u64 accp[8], ytp[8];
#pragma unroll
        for (int p = 0; p < 8; p++) { accp[p] = yp[p]; ytp[p] = yp[p]; }
#pragma unroll 1
        for (int sidx = 0; sidx < 4; sidx++) {
            const float ca = (sidx == 1 || sidx == 2) ? dt3 : dt6;
            const float cy = (sidx >= 2) ? dt : dth;
            const u64 cap = pack2(ca, ca);
            const u64 cyp = pack2(cy, cy);
            float pA[16], pB[16];
            matvec_half<false>(ytp, s.W1, q16, pA, pB);
            u64 tp[8];
#pragma unroll
            for (int p = 0; p < 8; p++) {
                float t0 = fast_tanh(CMB(pA, pB, 2 * p)     + b1q[2 * p]);
                float t1 = fast_tanh(CMB(pA, pB, 2 * p + 1) + b1q[2 * p + 1]);
                tp[p] = pack2(t0, t1);
            }
            matvec_half<false>(tp, s.W2, q16, pA, pB);
#pragma unroll
            for (int p = 0; p < 8; p++) {
                float k0 = CMB(pA, pB, 2 * p)     + b2q[2 * p];
                float k1 = CMB(pA, pB, 2 * p + 1) + b2q[2 * p + 1];
                u64 kp = pack2(k0, k1);
                accp[p] = ffma2(cap, kp, accp[p]);
                ytp[p]  = ffma2(cyp, kp, yp[p]);   // dead at sidx==3
            }
        }
#pragma unroll
        for (int p = 0; p < 8; p++) yp[p] = accp[p];
    }
}

// ---------- GRU cell (PyTorch gate order r,z,n), packed state hp[8] ----------
__device__ __forceinline__ void gru(u64* __restrict__ hp,
                                    const float* __restrict__ xg,
                                    int q16, const SW& s) {
    u64 xp[8];
    {
        const ulonglong2* x2 = (const ulonglong2*)xg;   // 64B-aligned
#pragma unroll
        for (int c = 0; c < 4; c++) {
            ulonglong2 v = x2[c];
            xp[2 * c] = v.x; xp[2 * c + 1] = v.y;
        }
    }
    float pA[16], pB[16], r[16], z[16];

    // r gate: accumulate x- and h-matvec partials, single combine
    matvec_half<false>(xp, s.Wih, q16, pA, pB);
    matvec_half<true>(hp, s.Whh, q16, pA, pB);
#pragma unroll
    for (int i = 0; i < 16; i++)
        r[i] = fast_sigmoid(CMB(pA, pB, i) + s.bih[q16 + i] + s.bhh[q16 + i]);

    // z gate
    matvec_half<false>(xp, s.Wih + HH * DIMI, q16, pA, pB);
    matvec_half<true>(hp, s.Whh + HH * HH, q16, pA, pB);
#pragma unroll
    for (int i = 0; i < 16; i++)
        z[i] = fast_sigmoid(CMB(pA, pB, i) + s.bih[HH + q16 + i] + s.bhh[HH + q16 + i]);

    // n gate: gi and gh kept separate (r scales only the h-path)
    float gi[16];
    matvec_half<false>(xp, s.Wih + 2 * HH * DIMI, q16, pA, pB);
#pragma unroll
    for (int i = 0; i < 16; i++)
        gi[i] = CMB(pA, pB, i) + s.bih[2 * HH + q16 + i];
    matvec_half<false>(hp, s.Whh + 2 * HH * HH, q16, pA, pB);
#pragma unroll
    for (int p = 0; p < 8; p++) {
        float h0f, h1f; unpack2(hp[p], h0f, h1f);
        float o[2];
#pragma unroll
        for (int qq = 0; qq < 2; qq++) {
            int i = 2 * p + qq;
            float gh = CMB(pA, pB, i) + s.bhh[2 * HH + q16 + i];
            float n  = fast_tanh(gi[i] + r[i] * gh);
            float hv = qq ? h1f : h0f;
            o[qq] = (1.0f - z[i]) * n + z[i] * hv;
        }
        hp[p] = pack2(o[0], o[1]);
    }
}

__device__ __forceinline__ void store_relu(float* __restrict__ dst,
                                           const u64* __restrict__ yp) {
#pragma unroll
    for (int p = 0; p < 8; p++) {
        float a, b; unpack2(yp[p], a, b);
        ((float2*)dst)[p] = make_float2(fmaxf(a, 0.0f), fmaxf(b, 0.0f));
    }
}

__global__ void __launch_bounds__(128) ode_gru_kernel(
    const float* __restrict__ inputs,   // [B, 28, 32]
    const float* __restrict__ h0,       // [B, 32]
    const float* __restrict__ Wih, const float* __restrict__ Whh,
    const float* __restrict__ bih, const float* __restrict__ bhh,
    const float* __restrict__ W1,  const float* __restrict__ b1,
    const float* __restrict__ W2,  const float* __restrict__ b2,
    float* __restrict__ out)            // [2, B, 32]
{
    __shared__ SW s;
    const int tid = threadIdx.x;

    for (int i = tid; i < HH * HH; i += 128) { s.W1[i] = W1[i]; s.W2[i] = W2[i]; }
    for (int i = tid; i < 3 * HH * DIMI; i += 128) { s.Wih[i] = Wih[i]; s.Whh[i] = Whh[i]; }
    if (tid < HH)     { s.b1[tid]  = b1[tid];  s.b2[tid]  = b2[tid]; }
    if (tid < 3 * HH) { s.bih[tid] = bih[tid]; s.bhh[tid] = bhh[tid]; }
    __syncthreads();

    const int gt  = blockIdx.x * 128 + tid;  // 2 lanes per batch row
    const int row = gt >> 1;
    const int q16 = (gt & 1) * 16;           // this lane's element-half offset

    u64 yp[8];
    {
        const ulonglong2* h02 = (const ulonglong2*)(h0 + (size_t)row * HH + q16);
#pragma unroll
        for (int c = 0; c < 4; c++) {
            ulonglong2 v = h02[c];
            yp[2 * c] = v.x; yp[2 * c + 1] = v.y;
        }
    }

    const float* xbase = inputs + (size_t)row * SEQT * DIMI + q16;

    rk4(yp, 0.1f, q16, s);                        // initial span [0,1]
#pragma unroll 1
    for (int t = 0; t < SEQT - 1; t++) {          // steps 0..26
        gru(yp, xbase + t * DIMI, q16, s);
        rk4(yp, 0.1f, q16, s);
    }
    // step 27: GRU -> h_start, then span-14 integration -> h_end
    gru(yp, xbase + (SEQT - 1) * DIMI, q16, s);
    store_relu(out + (size_t)row * HH + q16, yp);
    rk4(yp, 1.4f, q16, s);
    store_relu(out + ((size_t)BATCH + row) * HH + q16, yp);
}

extern "C" void kernel_launch(void* const* d_in, const int* in_sizes, int n_in,
                              void* d_out, int out_size) {
    (void)in_sizes; (void)n_in; (void)out_size;
    ode_gru_kernel<<<(2 * BATCH) / 128, 128>>>(
        (const float*)d_in[0], (const float*)d_in[1],
        (const float*)d_in[2], (const float*)d_in[3],
        (const float*)d_in[4], (const float*)d_in[5],
        (const float*)d_in[6], (const float*)d_in[7],
        (const float*)d_in[8], (const float*)d_in[9],
        (float*)d_out);
}

// round 11
// speedup vs baseline: 2.5103x; 1.2808x over previous
#include <cuda_runtime.h>

typedef unsigned long long u64;

#define BATCH  32768
#define SEQT   28
#define DIMI   32
#define HH     32
#define NSTEPS 10

// ---------- packed f32x2 helpers (sm_103a) ----------
__device__ __forceinline__ u64 ffma2(u64 a, u64 b, u64 c) {
    u64 d;
    asm("fma.rn.f32x2 %0, %1, %2, %3;" : "=l"(d) : "l"(a), "l"(b), "l"(c));
    return d;
}
__device__ __forceinline__ u64 fadd2(u64 a, u64 b) {
    u64 d;
    asm("add.rn.f32x2 %0, %1, %2;" : "=l"(d) : "l"(a), "l"(b));
    return d;
}
__device__ __forceinline__ u64 pack2(float a, float b) {
    u64 d;
    asm("mov.b64 %0, {%1, %2};" : "=l"(d) : "f"(a), "f"(b));
    return d;
}
__device__ __forceinline__ void unpack2(u64 a, float& lo, float& hi) {
    asm("mov.b64 {%0, %1}, %2;" : "=f"(lo), "=f"(hi) : "l"(a));
}
__device__ __forceinline__ float hsum2(u64 a) {
    float lo, hi; unpack2(a, lo, hi);
    return lo + hi;
}

// MUFU.EX2-based transcendentals (~1e-7 rel err)
__device__ __forceinline__ float fast_tanh(float x) {
    float e = __expf(2.0f * x);
    return 1.0f - __fdividef(2.0f, e + 1.0f);
}
__device__ __forceinline__ float fast_sigmoid(float x) {
    return __fdividef(1.0f, 1.0f + __expf(-x));
}

struct __align__(16) SW {
    float W1[HH * HH];
    float W2[HH * HH];
    float b1[HH];
    float b2[HH];
    float Wih[3 * HH * DIMI];
    float Whh[3 * HH * HH];
    float bih[3 * HH];
    float bhh[3 * HH];
};

// Dual-row packed matvec with immediate per-output combine.
// v0/v1: 8 f32x2 pairs each = the lane's 16 k-elems of rows 0/1.
// Each weight LDS.128 feeds BOTH rows' FFMA2 chains (halves LDS per row).
// r0[i]/r1[i] (+)= full dot of output j = q16+i (combined via shfl_xor
// inside the i-iteration, so no long-lived partial arrays).
// unroll 4 is load-bearing (ptxas load-hoisting; see R8 vs R2/R5/R6/R7).
template <bool ACC>
__device__ __forceinline__ void mv2(const u64* __restrict__ v0,
                                    const u64* __restrict__ v1,
                                    const float* __restrict__ Wbase,
                                    int q16,
                                    float* __restrict__ r0,
                                    float* __restrict__ r1) {
    const int jB = 16 - q16;
#pragma unroll 4
    for (int i = 0; i < 16; i++) {
        const ulonglong2* rA = (const ulonglong2*)(Wbase + (q16 + i) * HH + q16);
        const ulonglong2* rB = (const ulonglong2*)(Wbase + (jB + i) * HH + q16);
        u64 a0 = 0ull, a1 = 0ull, b0 = 0ull, b1 = 0ull;
        u64 c0 = 0ull, c1 = 0ull, d0 = 0ull, d1 = 0ull;
#pragma unroll
        for (int c = 0; c < 4; c++) {
            ulonglong2 wa = rA[c];
            ulonglong2 wb = rB[c];
            a0 = ffma2(v0[2 * c],     wa.x, a0);
            a1 = ffma2(v0[2 * c + 1], wa.y, a1);
            b0 = ffma2(v0[2 * c],     wb.x, b0);
            b1 = ffma2(v0[2 * c + 1], wb.y, b1);
            c0 = ffma2(v1[2 * c],     wa.x, c0);
            c1 = ffma2(v1[2 * c + 1], wa.y, c1);
            d0 = ffma2(v1[2 * c],     wb.x, d0);
            d1 = ffma2(v1[2 * c + 1], wb.y, d1);
        }
        float sA0 = hsum2(fadd2(a0, a1));
        float sB0 = hsum2(fadd2(b0, b1));
        float sA1 = hsum2(fadd2(c0, c1));
        float sB1 = hsum2(fadd2(d0, d1));
        float f0 = sA0 + __shfl_xor_sync(0xffffffffu, sB0, 1);
        float f1 = sA1 + __shfl_xor_sync(0xffffffffu, sB1, 1);
        if (ACC) { r0[i] += f0; r1[i] += f1; }
        else     { r0[i] = f0;  r1[i] = f1; }
    }
}

// ---------- RK4 over one span, dual-row packed state ----------
__device__ __forceinline__ void rk4(u64* __restrict__ y0, u64* __restrict__ y1,
                                    float dt, int q16, const SW& s) {
    const float dt6 = dt * (1.0f / 6.0f);
    const float dt3 = dt * (1.0f / 3.0f);
    const float dth = dt * 0.5f;
    const float* b1q = s.b1 + q16;
    const float* b2q = s.b2 + q16;
#pragma unroll 1
    for (int st = 0; st < NSTEPS; st++) {
        u64 acc0[8], acc1[8], yt0[8], yt1[8];
#pragma unroll
        for (int p = 0; p < 8; p++) {
            acc0[p] = y0[p]; yt0[p] = y0[p];
            acc1[p] = y1[p]; yt1[p] = y1[p];
        }
#pragma unroll 1
        for (int sidx = 0; sidx < 4; sidx++) {
            const float ca = (sidx == 1 || sidx == 2) ? dt3 : dt6;
            const float cy = (sidx >= 2) ? dt : dth;
            const u64 cap = pack2(ca, ca);
            const u64 cyp = pack2(cy, cy);
            float t0[16], t1[16];
            mv2<false>(yt0, yt1, s.W1, q16, t0, t1);
            u64 tp0[8], tp1[8];
#pragma unroll
            for (int p = 0; p < 8; p++) {
                tp0[p] = pack2(fast_tanh(t0[2 * p] + b1q[2 * p]),
                               fast_tanh(t0[2 * p + 1] + b1q[2 * p + 1]));
                tp1[p] = pack2(fast_tanh(t1[2 * p] + b1q[2 * p]),
                               fast_tanh(t1[2 * p + 1] + b1q[2 * p + 1]));
            }
            mv2<false>(tp0, tp1, s.W2, q16, t0, t1);
#pragma unroll
            for (int p = 0; p < 8; p++) {
                u64 k0 = pack2(t0[2 * p] + b2q[2 * p], t0[2 * p + 1] + b2q[2 * p + 1]);
                u64 k1 = pack2(t1[2 * p] + b2q[2 * p], t1[2 * p + 1] + b2q[2 * p + 1]);
                acc0[p] = ffma2(cap, k0, acc0[p]);
                yt0[p]  = ffma2(cyp, k0, y0[p]);   // dead at sidx==3
                acc1[p] = ffma2(cap, k1, acc1[p]);
                yt1[p]  = ffma2(cyp, k1, y1[p]);
            }
        }
#pragma unroll
        for (int p = 0; p < 8; p++) { y0[p] = acc0[p]; y1[p] = acc1[p]; }
    }
}

// ---------- GRU cell (PyTorch gate order r,z,n), dual-row ----------
__device__ __forceinline__ void gru(u64* __restrict__ h0, u64* __restrict__ h1,
                                    const float* __restrict__ xg0,
                                    const float* __restrict__ xg1,
                                    int q16, const SW& s) {
    u64 x0[8], x1[8];
    {
        const ulonglong2* a = (const ulonglong2*)xg0;
        const ulonglong2* b = (const ulonglong2*)xg1;
#pragma unroll
        for (int c = 0; c < 4; c++) {
            ulonglong2 va = a[c], vb = b[c];
            x0[2 * c] = va.x; x0[2 * c + 1] = va.y;
            x1[2 * c] = vb.x; x1[2 * c + 1] = vb.y;
        }
    }
    float r0[16], r1[16], z0[16], z1[16];

    // r gate: accumulate x- and h-matvecs, then sigmoid
    mv2<false>(x0, x1, s.Wih, q16, r0, r1);
    mv2<true>(h0, h1, s.Whh, q16, r0, r1);
#pragma unroll
    for (int i = 0; i < 16; i++) {
        float bb = s.bih[q16 + i] + s.bhh[q16 + i];
        r0[i] = fast_sigmoid(r0[i] + bb);
        r1[i] = fast_sigmoid(r1[i] + bb);
    }

    // z gate
    mv2<false>(x0, x1, s.Wih + HH * DIMI, q16, z0, z1);
    mv2<true>(h0, h1, s.Whh + HH * HH, q16, z0, z1);
#pragma unroll
    for (int i = 0; i < 16; i++) {
        float bb = s.bih[HH + q16 + i] + s.bhh[HH + q16 + i];
        z0[i] = fast_sigmoid(z0[i] + bb);
        z1[i] = fast_sigmoid(z1[i] + bb);
    }

    // n gate: gi (x-path) and gh (h-path) kept separate
    float gi0[16], gi1[16], gh0[16], gh1[16];
    mv2<false>(x0, x1, s.Wih + 2 * HH * DIMI, q16, gi0, gi1);
    mv2<false>(h0, h1, s.Whh + 2 * HH * HH, q16, gh0, gh1);
#pragma unroll
    for (int p = 0; p < 8; p++) {
        float ha, hb; float o[2];
        unpack2(h0[p], ha, hb);
#pragma unroll
        for (int qq = 0; qq < 2; qq++) {
            int i = 2 * p + qq;
            float hn = gh0[i] + s.bhh[2 * HH + q16 + i];
            float n  = fast_tanh(gi0[i] + s.bih[2 * HH + q16 + i] + r0[i] * hn);
            float hv = qq ? hb : ha;
            o[qq] = (1.0f - z0[i]) * n + z0[i] * hv;
        }
        h0[p] = pack2(o[0], o[1]);
        unpack2(h1[p], ha, hb);
#pragma unroll
        for (int qq = 0; qq < 2; qq++) {
            int i = 2 * p + qq;
            float hn = gh1[i] + s.bhh[2 * HH + q16 + i];
            float n  = fast_tanh(gi1[i] + s.bih[2 * HH + q16 + i] + r1[i] * hn);
            float hv = qq ? hb : ha;
            o[qq] = (1.0f - z1[i]) * n + z1[i] * hv;
        }
        h1[p] = pack2(o[0], o[1]);
    }
}

__device__ __forceinline__ void store_relu(float* __restrict__ dst,
                                           const u64* __restrict__ yp) {
#pragma unroll
    for (int p = 0; p < 8; p++) {
        float a, b; unpack2(yp[p], a, b);
        ((float2*)dst)[p] = make_float2(fmaxf(a, 0.0f), fmaxf(b, 0.0f));
    }
}

__global__ void __launch_bounds__(64) ode_gru_kernel(
    const float* __restrict__ inputs,   // [B, 28, 32]
    const float* __restrict__ h0in,     // [B, 32]
    const float* __restrict__ Wih, const float* __restrict__ Whh,
    const float* __restrict__ bih, const float* __restrict__ bhh,
    const float* __restrict__ W1,  const float* __restrict__ b1,
    const float* __restrict__ W2,  const float* __restrict__ b2,
    float* __restrict__ out)            // [2, B, 32]
{
    __shared__ SW s;
    const int tid = threadIdx.x;

    for (int i = tid; i < HH * HH; i += 64) { s.W1[i] = W1[i]; s.W2[i] = W2[i]; }
    for (int i = tid; i < 3 * HH * DIMI; i += 64) { s.Wih[i] = Wih[i]; s.Whh[i] = Whh[i]; }
    if (tid < HH) { s.b1[tid] = b1[tid]; s.b2[tid] = b2[tid]; }
    for (int i = tid; i < 3 * HH; i += 64) { s.bih[i] = bih[i]; s.bhh[i] = bhh[i]; }
    __syncthreads();

    const int gt   = blockIdx.x * 64 + tid;   // 2 lanes per row-pair
    const int pair = gt >> 1;                 // row-pair index
    const int q16  = (gt & 1) * 16;           // lane's element-half offset
    const int row0 = 2 * pair;
    const int row1 = 2 * pair + 1;

    u64 y0[8], y1[8];
    {
        const ulonglong2* a = (const ulonglong2*)(h0in + (size_t)row0 * HH + q16);
        const ulonglong2* b = (const ulonglong2*)(h0in + (size_t)row1 * HH + q16);
#pragma unroll
        for (int c = 0; c < 4; c++) {
            ulonglong2 va = a[c], vb = b[c];
            y0[2 * c] = va.x; y0[2 * c + 1] = va.y;
            y1[2 * c] = vb.x; y1[2 * c + 1] = vb.y;
        }
    }

    const float* xb0 = inputs + (size_t)row0 * SEQT * DIMI + q16;
    const float* xb1 = inputs + (size_t)row1 * SEQT * DIMI + q16;

    rk4(y0, y1, 0.1f, q16, s);                    // initial span [0,1]
#pragma unroll 1
    for (int t = 0; t < SEQT - 1; t++) {          // steps 0..26
        gru(y0, y1, xb0 + t * DIMI, xb1 + t * DIMI, q16, s);
        rk4(y0, y1, 0.1f, q16, s);
    }
    // step 27: GRU -> h_start, then span-14 integration -> h_end
    gru(y0, y1, xb0 + (SEQT - 1) * DIMI, xb1 + (SEQT - 1) * DIMI, q16, s);
    store_relu(out + (size_t)row0 * HH + q16, y0);
    store_relu(out + (size_t)row1 * HH + q16, y1);
    rk4(y0, y1, 1.4f, q16, s);
    store_relu(out + ((size_t)BATCH + row0) * HH + q16, y0);
    store_relu(out + ((size_t)BATCH + row1) * HH + q16, y1);
}

extern "C" void kernel_launch(void* const* d_in, const int* in_sizes, int n_in,
                              void* d_out, int out_size) {
    (void)in_sizes; (void)n_in; (void)out_size;
    ode_gru_kernel<<<BATCH / 64, 64>>>(
        (const float*)d_in[0], (const float*)d_in[1],
        (const float*)d_in[2], (const float*)d_in[3],
        (const float*)d_in[4], (const float*)d_in[5],
        (const float*)d_in[6], (const float*)d_in[7],
        (const float*)d_in[8], (const float*)d_in[9],
        (float*)d_out);
}